// round 2
// baseline (speedup 1.0000x reference)
#include <cuda_runtime.h>
#include <math.h>

// Problem constants: B=2, N=2048, C=1024, H=16, D=64
// Q/K/V layout: [bh=32][n=2048][128] where dim 0..63 = real part, 64..127 = imag part.

#define ATTN_SMEM 103424  // (2*128*68 + 64*132) * 4 bytes

__device__ float g_q[32 * 2048 * 128];
__device__ float g_k[32 * 2048 * 128];
__device__ float g_v[32 * 2048 * 128];
__device__ float g_ao[32 * 2048 * 128];   // attention output, same layout
__device__ float g_z[4096 * 2048];        // merged heads: [out_r | out_i] per token
__device__ float g_wc[1024 * 2048];       // combined output weight
__device__ float g_fb[1024];              // combined output bias

// ---------------------------------------------------------------------------
// Combined output weight: Wc[o][k<1024]   = or_w[o][k]      + 0.1*oi_w[o][k]
//                         Wc[o][k>=1024]  = 0.1*or_w[o][k'] -     oi_w[o][k']
// bias fb[o] = 1.1*or_b[o] - 0.9*oi_b[o]
// ---------------------------------------------------------------------------
__global__ void __launch_bounds__(256) make_wc_kernel(
    const float* __restrict__ orw, const float* __restrict__ oiw,
    const float* __restrict__ orb, const float* __restrict__ oib)
{
    int idx = blockIdx.x * 256 + threadIdx.x;   // float4 index over [1024][2048]
    int o = idx >> 9;                            // 512 float4 per row
    int k = (idx & 511) << 2;
    float4 r;
    if (k < 1024) {
        float4 a = *(const float4*)(orw + o * 1024 + k);
        float4 b = *(const float4*)(oiw + o * 1024 + k);
        r.x = a.x + 0.1f * b.x; r.y = a.y + 0.1f * b.y;
        r.z = a.z + 0.1f * b.z; r.w = a.w + 0.1f * b.w;
    } else {
        int kk = k - 1024;
        float4 a = *(const float4*)(orw + o * 1024 + kk);
        float4 b = *(const float4*)(oiw + o * 1024 + kk);
        r.x = 0.1f * a.x - b.x; r.y = 0.1f * a.y - b.y;
        r.z = 0.1f * a.z - b.z; r.w = 0.1f * a.w - b.w;
    }
    *(float4*)(g_wc + o * 2048 + k) = r;
    if ((idx & 511) == 0)
        g_fb[o] = 1.1f * orb[o] - 0.9f * oib[o];
}

// ---------------------------------------------------------------------------
// Input projection GEMM. Computes Y[m, o] = sum_c X[m,c] * W[o,c] + bias[o]
// for o in [0,2048): o<1024 -> real weight, o>=1024 -> imag weight.
// Output scattered into [bh][n][128] layout (which selects g_q / g_k / g_v).
// BM=BN=128, BK=16, 256 threads, 8x8 per thread.
// ---------------------------------------------------------------------------
__global__ void __launch_bounds__(256) proj_gemm_kernel(
    const float* __restrict__ X,
    const float* __restrict__ Wr, const float* __restrict__ Wi,
    const float* __restrict__ br, const float* __restrict__ bi,
    int which)
{
    __shared__ float As[16][132];
    __shared__ float Bs[16][132];
    float* Out = (which == 0) ? g_q : (which == 1) ? g_k : g_v;

    const int t  = threadIdx.x;
    const int tx = t & 15, ty = t >> 4;
    const int m0 = blockIdx.y * 128;
    const int o0 = blockIdx.x * 128;
    const int lr = t >> 2;            // 0..63
    const int lk = (t & 3) * 4;       // 0,4,8,12

    const float* a0p = X + (m0 + lr) * 1024;
    const float* a1p = X + (m0 + lr + 64) * 1024;
    int ow0 = o0 + lr;
    int ow1 = o0 + lr + 64;
    const float* b0p = (ow0 < 1024) ? (Wr + ow0 * 1024) : (Wi + (ow0 - 1024) * 1024);
    const float* b1p = (ow1 < 1024) ? (Wr + ow1 * 1024) : (Wi + (ow1 - 1024) * 1024);

    float acc[8][8];
    #pragma unroll
    for (int i = 0; i < 8; i++)
        #pragma unroll
        for (int j = 0; j < 8; j++) acc[i][j] = 0.f;

    for (int k0 = 0; k0 < 1024; k0 += 16) {
        float4 a0 = *(const float4*)(a0p + k0 + lk);
        float4 a1 = *(const float4*)(a1p + k0 + lk);
        float4 b0 = *(const float4*)(b0p + k0 + lk);
        float4 b1 = *(const float4*)(b1p + k0 + lk);
        As[lk + 0][lr] = a0.x; As[lk + 1][lr] = a0.y; As[lk + 2][lr] = a0.z; As[lk + 3][lr] = a0.w;
        As[lk + 0][lr + 64] = a1.x; As[lk + 1][lr + 64] = a1.y; As[lk + 2][lr + 64] = a1.z; As[lk + 3][lr + 64] = a1.w;
        Bs[lk + 0][lr] = b0.x; Bs[lk + 1][lr] = b0.y; Bs[lk + 2][lr] = b0.z; Bs[lk + 3][lr] = b0.w;
        Bs[lk + 0][lr + 64] = b1.x; Bs[lk + 1][lr + 64] = b1.y; Bs[lk + 2][lr + 64] = b1.z; Bs[lk + 3][lr + 64] = b1.w;
        __syncthreads();
        #pragma unroll
        for (int k = 0; k < 16; k++) {
            float a[8], b[8];
            *(float4*)&a[0] = *(const float4*)&As[k][ty * 8];
            *(float4*)&a[4] = *(const float4*)&As[k][ty * 8 + 4];
            *(float4*)&b[0] = *(const float4*)&Bs[k][tx * 8];
            *(float4*)&b[4] = *(const float4*)&Bs[k][tx * 8 + 4];
            #pragma unroll
            for (int i = 0; i < 8; i++)
                #pragma unroll
                for (int j = 0; j < 8; j++)
                    acc[i][j] = fmaf(a[i], b[j], acc[i][j]);
        }
        __syncthreads();
    }

    // epilogue: scatter into [bh][n][128]
    int oB = o0 + tx * 8;
    int part = oB >> 10;
    int oo = oB & 1023;
    int h = oo >> 6;
    int dd = oo & 63;
    const float* bptr = part ? bi : br;
    float4 bias0 = *(const float4*)(bptr + oo);
    float4 bias1 = *(const float4*)(bptr + oo + 4);
    #pragma unroll
    for (int i = 0; i < 8; i++) {
        int m = m0 + ty * 8 + i;
        int b_ = m >> 11;
        int nn = m & 2047;
        float* dst = Out + ((size_t)(((b_ << 4) + h) * 2048 + nn)) * 128 + part * 64 + dd;
        float4 r0 = make_float4(acc[i][0] + bias0.x, acc[i][1] + bias0.y,
                                acc[i][2] + bias0.z, acc[i][3] + bias0.w);
        float4 r1 = make_float4(acc[i][4] + bias1.x, acc[i][5] + bias1.y,
                                acc[i][6] + bias1.z, acc[i][7] + bias1.w);
        *(float4*)dst = r0;
        *(float4*)(dst + 4) = r1;
    }
}

// ---------------------------------------------------------------------------
// Fused complex-magnitude flash attention.
// Per block: one (bh, 64-query tile). Loops over 2048 keys in tiles of 64.
//   sr = qr.kr + qi.ki ; si = qi.kr - qr.ki ; mag = 0.125*sqrt(sr^2+si^2)
//   online softmax over mag; out = softmax @ [vr|vi]
// Threads: 16x16; scores 4x4/thread; output rows ty*4..+3, cols tx*4 & 64+tx*4.
// ---------------------------------------------------------------------------
__global__ void __launch_bounds__(256, 2) attn_kernel()
{
    extern __shared__ float sm[];
    float* Qs = sm;                   // [128][68] transposed (dim-major)
    float* KP = sm + 128 * 68;        // [128][68] K transposed; reused as P [64][68]
    float* Vs = sm + 2 * 128 * 68;    // [64][132]

    const int t  = threadIdx.x;
    const int tx = t & 15;
    const int ty = t >> 4;
    const int bh = blockIdx.y;
    const int q0 = blockIdx.x * 64;

    const float* Qg = g_q + ((size_t)bh * 2048 + q0) * 128;
    const float* Kg = g_k + (size_t)bh * 2048 * 128;
    const float* Vg = g_v + (size_t)bh * 2048 * 128;

    const int lr = t >> 2;   // 0..63
    const int lc = t & 3;    // 0..3

    // load Q tile, transposing into Qs[d][n]
    #pragma unroll
    for (int i = 0; i < 8; i++) {
        int d4 = lc + i * 4;
        float4 v = *(const float4*)(Qg + lr * 128 + d4 * 4);
        int d = d4 * 4;
        Qs[(d + 0) * 68 + lr] = v.x;
        Qs[(d + 1) * 68 + lr] = v.y;
        Qs[(d + 2) * 68 + lr] = v.z;
        Qs[(d + 3) * 68 + lr] = v.w;
    }

    float m_run[4], l_run[4];
    float oacc[4][8];
    #pragma unroll
    for (int i = 0; i < 4; i++) {
        m_run[i] = -3.0e38f;
        l_run[i] = 0.f;
        #pragma unroll
        for (int j = 0; j < 8; j++) oacc[i][j] = 0.f;
    }

    for (int k0 = 0; k0 < 2048; k0 += 64) {
        // load K (transposed) and V tiles
        #pragma unroll
        for (int i = 0; i < 8; i++) {
            int d4 = lc + i * 4;
            float4 v = *(const float4*)(Kg + (size_t)(k0 + lr) * 128 + d4 * 4);
            int d = d4 * 4;
            KP[(d + 0) * 68 + lr] = v.x;
            KP[(d + 1) * 68 + lr] = v.y;
            KP[(d + 2) * 68 + lr] = v.z;
            KP[(d + 3) * 68 + lr] = v.w;
        }
        #pragma unroll
        for (int i = 0; i < 8; i++) {
            int d4 = lc + i * 4;
            float4 v = *(const float4*)(Vg + (size_t)(k0 + lr) * 128 + d4 * 4);
            *(float4*)(Vs + lr * 132 + d4 * 4) = v;
        }
        __syncthreads();

        float sr[4][4], si[4][4];
        #pragma unroll
        for (int i = 0; i < 4; i++)
            #pragma unroll
            for (int j = 0; j < 4; j++) { sr[i][j] = 0.f; si[i][j] = 0.f; }

        #pragma unroll 8
        for (int k = 0; k < 64; k++) {
            float qrv[4], qiv[4], krv[4], kiv[4];
            *(float4*)qrv = *(const float4*)(Qs + k * 68 + ty * 4);
            *(float4*)qiv = *(const float4*)(Qs + (64 + k) * 68 + ty * 4);
            *(float4*)krv = *(const float4*)(KP + k * 68 + tx * 4);
            *(float4*)kiv = *(const float4*)(KP + (64 + k) * 68 + tx * 4);
            #pragma unroll
            for (int i = 0; i < 4; i++)
                #pragma unroll
                for (int j = 0; j < 4; j++) {
                    sr[i][j] = fmaf(qrv[i], krv[j], sr[i][j]);
                    sr[i][j] = fmaf(qiv[i], kiv[j], sr[i][j]);
                    si[i][j] = fmaf(qiv[i], krv[j], si[i][j]);
                    si[i][j] = fmaf(-qrv[i], kiv[j], si[i][j]);
                }
        }
        __syncthreads();   // all done reading K region of KP

        // magnitude + online softmax; write P into KP
        #pragma unroll
        for (int i = 0; i < 4; i++) {
            float rowmax = -3.0e38f;
            #pragma unroll
            for (int j = 0; j < 4; j++) {
                float mag = 0.125f * sqrtf(sr[i][j] * sr[i][j] + si[i][j] * si[i][j]);
                sr[i][j] = mag;
                rowmax = fmaxf(rowmax, mag);
            }
            #pragma unroll
            for (int off = 8; off >= 1; off >>= 1)
                rowmax = fmaxf(rowmax, __shfl_xor_sync(0xffffffffu, rowmax, off, 16));
            float mnew = fmaxf(m_run[i], rowmax);
            float corr = __expf(m_run[i] - mnew);
            m_run[i] = mnew;
            float rsum = 0.f;
            #pragma unroll
            for (int j = 0; j < 4; j++) {
                float e = __expf(sr[i][j] - mnew);
                sr[i][j] = e;
                rsum += e;
            }
            #pragma unroll
            for (int off = 8; off >= 1; off >>= 1)
                rsum += __shfl_xor_sync(0xffffffffu, rsum, off, 16);
            l_run[i] = l_run[i] * corr + rsum;
            #pragma unroll
            for (int j = 0; j < 8; j++) oacc[i][j] *= corr;
            *(float4*)(KP + (ty * 4 + i) * 68 + tx * 4) = *(float4*)&sr[i][0];
        }
        __syncthreads();   // P visible

        // out += P @ Vcat
        #pragma unroll 8
        for (int kk = 0; kk < 64; kk++) {
            float v0[4], v1[4];
            *(float4*)v0 = *(const float4*)(Vs + kk * 132 + tx * 4);
            *(float4*)v1 = *(const float4*)(Vs + kk * 132 + 64 + tx * 4);
            #pragma unroll
            for (int i = 0; i < 4; i++) {
                float pv = KP[(ty * 4 + i) * 68 + kk];
                #pragma unroll
                for (int j = 0; j < 4; j++) {
                    oacc[i][j]     = fmaf(pv, v0[j], oacc[i][j]);
                    oacc[i][4 + j] = fmaf(pv, v1[j], oacc[i][4 + j]);
                }
            }
        }
        __syncthreads();   // done with P and V before next tile overwrites
    }

    float* Og = g_ao + ((size_t)bh * 2048 + q0) * 128;
    #pragma unroll
    for (int i = 0; i < 4; i++) {
        float inv = 1.f / l_run[i];
        float o0v[4], o1v[4];
        #pragma unroll
        for (int j = 0; j < 4; j++) {
            o0v[j] = oacc[i][j] * inv;
            o1v[j] = oacc[i][4 + j] * inv;
        }
        *(float4*)(Og + (ty * 4 + i) * 128 + tx * 4) = *(float4*)o0v;
        *(float4*)(Og + (ty * 4 + i) * 128 + 64 + tx * 4) = *(float4*)o1v;
    }
}

// ---------------------------------------------------------------------------
// Merge heads: g_ao [bh][n][128] -> g_z [b*2048+n][2048] = [out_r(1024) | out_i(1024)]
// ---------------------------------------------------------------------------
__global__ void __launch_bounds__(256) repack_kernel()
{
    int idx = blockIdx.x * 256 + threadIdx.x;   // float4 index, 2M total
    int d4 = idx & 31;
    int nn = (idx >> 5) & 2047;
    int bh = idx >> 16;
    float4 v = *(const float4*)(g_ao + (size_t)idx * 4);
    int b_ = bh >> 4, h = bh & 15;
    int d = d4 << 2;
    int part = d >> 6;
    int dl = d & 63;
    int col = part * 1024 + h * 64 + dl;
    *(float4*)(g_z + ((size_t)(b_ * 2048 + nn)) * 2048 + col) = v;
}

// ---------------------------------------------------------------------------
// Final GEMM: out[m][o] = sum_k g_z[m][k] * g_wc[o][k] + g_fb[o]
// M=4096, O=1024, K=2048.
// ---------------------------------------------------------------------------
__global__ void __launch_bounds__(256) final_gemm_kernel(float* __restrict__ Outp)
{
    __shared__ float As[16][132];
    __shared__ float Bs[16][132];

    const int t  = threadIdx.x;
    const int tx = t & 15, ty = t >> 4;
    const int m0 = blockIdx.y * 128;
    const int o0 = blockIdx.x * 128;
    const int lr = t >> 2;
    const int lk = (t & 3) * 4;

    const float* a0p = g_z + (size_t)(m0 + lr) * 2048;
    const float* a1p = g_z + (size_t)(m0 + lr + 64) * 2048;
    const float* b0p = g_wc + (size_t)(o0 + lr) * 2048;
    const float* b1p = g_wc + (size_t)(o0 + lr + 64) * 2048;

    float acc[8][8];
    #pragma unroll
    for (int i = 0; i < 8; i++)
        #pragma unroll
        for (int j = 0; j < 8; j++) acc[i][j] = 0.f;

    for (int k0 = 0; k0 < 2048; k0 += 16) {
        float4 a0 = *(const float4*)(a0p + k0 + lk);
        float4 a1 = *(const float4*)(a1p + k0 + lk);
        float4 b0 = *(const float4*)(b0p + k0 + lk);
        float4 b1 = *(const float4*)(b1p + k0 + lk);
        As[lk + 0][lr] = a0.x; As[lk + 1][lr] = a0.y; As[lk + 2][lr] = a0.z; As[lk + 3][lr] = a0.w;
        As[lk + 0][lr + 64] = a1.x; As[lk + 1][lr + 64] = a1.y; As[lk + 2][lr + 64] = a1.z; As[lk + 3][lr + 64] = a1.w;
        Bs[lk + 0][lr] = b0.x; Bs[lk + 1][lr] = b0.y; Bs[lk + 2][lr] = b0.z; Bs[lk + 3][lr] = b0.w;
        Bs[lk + 0][lr + 64] = b1.x; Bs[lk + 1][lr + 64] = b1.y; Bs[lk + 2][lr + 64] = b1.z; Bs[lk + 3][lr + 64] = b1.w;
        __syncthreads();
        #pragma unroll
        for (int k = 0; k < 16; k++) {
            float a[8], b[8];
            *(float4*)&a[0] = *(const float4*)&As[k][ty * 8];
            *(float4*)&a[4] = *(const float4*)&As[k][ty * 8 + 4];
            *(float4*)&b[0] = *(const float4*)&Bs[k][tx * 8];
            *(float4*)&b[4] = *(const float4*)&Bs[k][tx * 8 + 4];
            #pragma unroll
            for (int i = 0; i < 8; i++)
                #pragma unroll
                for (int j = 0; j < 8; j++)
                    acc[i][j] = fmaf(a[i], b[j], acc[i][j]);
        }
        __syncthreads();
    }

    float4 fb0 = *(const float4*)(g_fb + o0 + tx * 8);
    float4 fb1 = *(const float4*)(g_fb + o0 + tx * 8 + 4);
    #pragma unroll
    for (int i = 0; i < 8; i++) {
        int m = m0 + ty * 8 + i;
        float* dst = Outp + (size_t)m * 1024 + o0 + tx * 8;
        float4 r0 = make_float4(acc[i][0] + fb0.x, acc[i][1] + fb0.y,
                                acc[i][2] + fb0.z, acc[i][3] + fb0.w);
        float4 r1 = make_float4(acc[i][4] + fb1.x, acc[i][5] + fb1.y,
                                acc[i][6] + fb1.z, acc[i][7] + fb1.w);
        *(float4*)dst = r0;
        *(float4*)(dst + 4) = r1;
    }
}

// ---------------------------------------------------------------------------
extern "C" void kernel_launch(void* const* d_in, const int* in_sizes, int n_in,
                              void* d_out, int out_size)
{
    const float* x    = (const float*)d_in[0];
    const float* qr_w = (const float*)d_in[1];
    const float* qr_b = (const float*)d_in[2];
    const float* qi_w = (const float*)d_in[3];
    const float* qi_b = (const float*)d_in[4];
    const float* kr_w = (const float*)d_in[5];
    const float* kr_b = (const float*)d_in[6];
    const float* ki_w = (const float*)d_in[7];
    const float* ki_b = (const float*)d_in[8];
    const float* vr_w = (const float*)d_in[9];
    const float* vr_b = (const float*)d_in[10];
    const float* vi_w = (const float*)d_in[11];
    const float* vi_b = (const float*)d_in[12];
    const float* or_w = (const float*)d_in[13];
    const float* or_b = (const float*)d_in[14];
    const float* oi_w = (const float*)d_in[15];
    const float* oi_b = (const float*)d_in[16];
    float* out = (float*)d_out;

    cudaFuncSetAttribute(attn_kernel, cudaFuncAttributeMaxDynamicSharedMemorySize, ATTN_SMEM);

    make_wc_kernel<<<2048, 256>>>(or_w, oi_w, or_b, oi_b);

    dim3 pg(16, 32);   // (O tiles = 2048/128, M tiles = 4096/128)
    proj_gemm_kernel<<<pg, 256>>>(x, qr_w, qi_w, qr_b, qi_b, 0);
    proj_gemm_kernel<<<pg, 256>>>(x, kr_w, ki_w, kr_b, ki_b, 1);
    proj_gemm_kernel<<<pg, 256>>>(x, vr_w, vi_w, vr_b, vi_b, 2);

    attn_kernel<<<dim3(32, 32), 256, ATTN_SMEM>>>();

    repack_kernel<<<8192, 256>>>();

    final_gemm_kernel<<<dim3(8, 32), 256>>>(out);
}

// round 3
// speedup vs baseline: 2.7364x; 2.7364x over previous
#include <cuda_runtime.h>
#include <cstdint>

// Problem: B=2, N=2048, C=1024, H=16, D=64
// Q/K/V layout: [bh=32][n=2048][128] with d 0..63 = real, 64..127 = imag.
// g_z layout: [b*2048+n][2048] = [out_r(1024) | out_i(1024)]

#define PROJ_SMEM (2 * 2 * 128 * 36 * 4)                              // 73728 B
#define ATT_SMEM  ((128 * 132 + 64 * 132 + 64 * 136 + 128 * 68) * 4)  // 171008 B

__device__ float g_q[32 * 2048 * 128];
__device__ float g_k[32 * 2048 * 128];
__device__ float g_v[32 * 2048 * 128];
__device__ float g_z[4096 * 2048];

// ---------------------------------------------------------------------------
// helpers
// ---------------------------------------------------------------------------
__device__ __forceinline__ float tf32f(float x) {
    uint32_t r;
    asm("cvt.rna.tf32.f32 %0, %1;" : "=r"(r) : "f"(x));
    return __int_as_float(r);
}

__device__ __forceinline__ void mma8(float* d,
                                     uint32_t a0, uint32_t a1, uint32_t a2, uint32_t a3,
                                     uint32_t b0, uint32_t b1) {
    asm volatile(
        "mma.sync.aligned.m16n8k8.row.col.f32.tf32.tf32.f32 "
        "{%0,%1,%2,%3}, {%4,%5,%6,%7}, {%8,%9}, {%0,%1,%2,%3};"
        : "+f"(d[0]), "+f"(d[1]), "+f"(d[2]), "+f"(d[3])
        : "r"(a0), "r"(a1), "r"(a2), "r"(a3), "r"(b0), "r"(b1));
}

// sqrt on the FMA pipe (no MUFU): bithack rsqrt + 2 Newton iterations
__device__ __forceinline__ float sqrt_nr(float h) {
    h = fmaxf(h, 1e-24f);
    float x = __int_as_float(0x5f3759df - (__float_as_int(h) >> 1));
    float hh = 0.5f * h;
    x = x * fmaf(-hh * x, x, 1.5f);
    x = x * fmaf(-hh * x, x, 1.5f);
    return h * x;
}

// exp2 on the FMA/ALU pipes (no MUFU). Valid for |z| < 120.
__device__ __forceinline__ float exp2p(float z) {
    float r = z + 12582912.0f;                      // round-to-nearest int
    int n = __float_as_int(r) - 0x4B400000;
    float f = z - (r - 12582912.0f);                // f in [-0.5, 0.5]
    float p = 1.3333558e-3f;
    p = fmaf(p, f, 9.6181291e-3f);
    p = fmaf(p, f, 5.5504109e-2f);
    p = fmaf(p, f, 2.4022651e-1f);
    p = fmaf(p, f, 6.9314718e-1f);
    p = fmaf(p, f, 1.0f);
    return __int_as_float(__float_as_int(p) + (n << 23));
}

// ---------------------------------------------------------------------------
// Input projections: one kernel, blockIdx.z = 0/1/2 -> Q/K/V.
// Y[m, o] = sum_c X[m,c]*W[o,c] + bias[o], o<1024 real W, o>=1024 imag W.
// BM=128, BN=128, BK=32, double-buffered smem, tf32 mma.
// 8 warps: 2(m) x 4(n); warp tile 64x32; per-thread 4x4 mma tiles.
// ---------------------------------------------------------------------------
__global__ void __launch_bounds__(256) proj_mma_kernel(
    const float* __restrict__ X,
    const float* __restrict__ qrw, const float* __restrict__ qrb,
    const float* __restrict__ qiw, const float* __restrict__ qib,
    const float* __restrict__ krw, const float* __restrict__ krb,
    const float* __restrict__ kiw, const float* __restrict__ kib,
    const float* __restrict__ vrw, const float* __restrict__ vrb,
    const float* __restrict__ viw, const float* __restrict__ vib)
{
    extern __shared__ float sm[];
    float* As = sm;                 // [2][128][36]
    float* Bs = sm + 2 * 128 * 36;  // [2][128][36]

    const int t = threadIdx.x;
    const int w = t >> 5, lane = t & 31, g = lane >> 2, tg = lane & 3;
    const int wm = w >> 2, wn = w & 3;
    const int z = blockIdx.z;
    const int bx = blockIdx.x;
    const int m0 = blockIdx.y * 128;
    const bool imag = bx >= 8;
    const float* W;
    const float* bias;
    float* Out;
    if (z == 0)      { W = imag ? qiw : qrw; bias = imag ? qib : qrb; Out = g_q; }
    else if (z == 1) { W = imag ? kiw : krw; bias = imag ? kib : krb; Out = g_k; }
    else             { W = imag ? viw : vrw; bias = imag ? vib : vrb; Out = g_v; }
    const int o0 = (bx & 7) * 128;

    int lrow[4], lc4[4];
    #pragma unroll
    for (int i = 0; i < 4; i++) { int idx = i * 256 + t; lrow[i] = idx >> 3; lc4[i] = (idx & 7) * 4; }

    const float* Ag = X + (size_t)m0 * 1024;
    const float* Bg = W + (size_t)o0 * 1024;

    float acc[4][4][4];
    #pragma unroll
    for (int a = 0; a < 4; a++)
        #pragma unroll
        for (int b = 0; b < 4; b++)
            #pragma unroll
            for (int c = 0; c < 4; c++) acc[a][b][c] = 0.f;

    float4 pa[4], pb[4];
    #pragma unroll
    for (int i = 0; i < 4; i++) {
        pa[i] = *(const float4*)(Ag + lrow[i] * 1024 + lc4[i]);
        pb[i] = *(const float4*)(Bg + lrow[i] * 1024 + lc4[i]);
    }
    #pragma unroll
    for (int i = 0; i < 4; i++) {
        float* d = As + lrow[i] * 36 + lc4[i];
        d[0] = tf32f(pa[i].x); d[1] = tf32f(pa[i].y); d[2] = tf32f(pa[i].z); d[3] = tf32f(pa[i].w);
        float* e = Bs + lrow[i] * 36 + lc4[i];
        e[0] = tf32f(pb[i].x); e[1] = tf32f(pb[i].y); e[2] = tf32f(pb[i].z); e[3] = tf32f(pb[i].w);
    }
    __syncthreads();

    for (int ktile = 0; ktile < 32; ktile++) {
        const int cur = ktile & 1;
        if (ktile + 1 < 32) {
            int k0 = (ktile + 1) * 32;
            #pragma unroll
            for (int i = 0; i < 4; i++) {
                pa[i] = *(const float4*)(Ag + lrow[i] * 1024 + k0 + lc4[i]);
                pb[i] = *(const float4*)(Bg + lrow[i] * 1024 + k0 + lc4[i]);
            }
        }
        const float* Ab = As + cur * 128 * 36;
        const float* Bb = Bs + cur * 128 * 36;
        #pragma unroll
        for (int ks = 0; ks < 4; ks++) {
            const int col = 8 * ks + tg;
            uint32_t a[4][4];
            #pragma unroll
            for (int mt = 0; mt < 4; mt++) {
                const float* ap = Ab + (64 * wm + 16 * mt + g) * 36;
                a[mt][0] = __float_as_uint(ap[col]);
                a[mt][1] = __float_as_uint(ap[8 * 36 + col]);
                a[mt][2] = __float_as_uint(ap[col + 4]);
                a[mt][3] = __float_as_uint(ap[8 * 36 + col + 4]);
            }
            #pragma unroll
            for (int nt = 0; nt < 4; nt++) {
                const float* bp = Bb + (32 * wn + 8 * nt + g) * 36;
                uint32_t b0 = __float_as_uint(bp[col]);
                uint32_t b1 = __float_as_uint(bp[col + 4]);
                #pragma unroll
                for (int mt = 0; mt < 4; mt++)
                    mma8(acc[mt][nt], a[mt][0], a[mt][1], a[mt][2], a[mt][3], b0, b1);
            }
        }
        if (ktile + 1 < 32) {
            float* dA = As + (1 - cur) * 128 * 36;
            float* dB = Bs + (1 - cur) * 128 * 36;
            #pragma unroll
            for (int i = 0; i < 4; i++) {
                float* d = dA + lrow[i] * 36 + lc4[i];
                d[0] = tf32f(pa[i].x); d[1] = tf32f(pa[i].y); d[2] = tf32f(pa[i].z); d[3] = tf32f(pa[i].w);
                float* e = dB + lrow[i] * 36 + lc4[i];
                e[0] = tf32f(pb[i].x); e[1] = tf32f(pb[i].y); e[2] = tf32f(pb[i].z); e[3] = tf32f(pb[i].w);
            }
        }
        __syncthreads();
    }

    // epilogue: scatter into [bh][n][128] layout with bias
    const int part = imag ? 1 : 0;
    const int ob = o0 + 32 * wn;
    const int hh = ob >> 6;
    #pragma unroll
    for (int mt = 0; mt < 4; mt++) {
        int m = m0 + 64 * wm + 16 * mt + g;
        #pragma unroll
        for (int r = 0; r < 2; r++) {
            int mm = m + 8 * r;
            int b_ = mm >> 11, nn = mm & 2047;
            float* dst = Out + ((size_t)(b_ * 16 + hh) * 2048 + nn) * 128 + part * 64;
            #pragma unroll
            for (int nt = 0; nt < 4; nt++) {
                int o = ob + 8 * nt + 2 * tg;
                float2 bv = *(const float2*)(bias + o);
                *(float2*)(dst + (o & 63)) =
                    make_float2(acc[mt][nt][2 * r + 0] + bv.x, acc[mt][nt][2 * r + 1] + bv.y);
            }
        }
    }
}

// ---------------------------------------------------------------------------
// Fused complex-magnitude attention, tf32 mma + FMA-pipe softmax.
// Block = 128 queries x one bh. 8 warps, each owns 16 query rows.
// K-tiles of 64 keys. Fixed-shift softmax: p = exp2(0.18034*s - 11.5416)
//   == exp(0.125*|score| - 8); ratios identical to softmax, no overflow.
// Writes merged-head output directly into g_z.
// ---------------------------------------------------------------------------
__global__ void __launch_bounds__(256) attn_mma_kernel()
{
    extern __shared__ float sm[];
    float* Qs = sm;                  // [128][132] tf32
    float* Ks = Qs + 128 * 132;      // [64][132]  tf32
    float* Vs = Ks + 64 * 132;       // [64][136]  tf32
    float* Ps = Vs + 64 * 136;       // [128][68]  tf32 probs

    const int t = threadIdx.x;
    const int w = t >> 5, lane = t & 31, g = lane >> 2, tg = lane & 3;
    const int bh = blockIdx.y;
    const int q0 = blockIdx.x * 128;

    const float* Qg = g_q + ((size_t)bh * 2048 + q0) * 128;
    const float* Kg = g_k + (size_t)bh * 2048 * 128;
    const float* Vg = g_v + (size_t)bh * 2048 * 128;

    #pragma unroll
    for (int i = 0; i < 16; i++) {
        int idx = i * 256 + t;
        int row = idx >> 5, c4 = (idx & 31) * 4;
        float4 v = *(const float4*)(Qg + row * 128 + c4);
        float* d = Qs + row * 132 + c4;
        d[0] = tf32f(v.x); d[1] = tf32f(v.y); d[2] = tf32f(v.z); d[3] = tf32f(v.w);
    }

    float O[16][4];
    #pragma unroll
    for (int i = 0; i < 16; i++) { O[i][0] = 0.f; O[i][1] = 0.f; O[i][2] = 0.f; O[i][3] = 0.f; }
    float l0 = 0.f, l1 = 0.f;

    const int qrow = 16 * w;
    const float K1 = 0.18033688f;   // 0.125 * log2(e)
    const float K2 = -11.541560f;   // -8 * log2(e)

    for (int kt = 0; kt < 32; kt++) {
        __syncthreads();   // previous tile's consumers of Ks/Vs done (and Qs ready)
        const float* Kt = Kg + (size_t)kt * 64 * 128;
        const float* Vt = Vg + (size_t)kt * 64 * 128;
        #pragma unroll
        for (int i = 0; i < 8; i++) {
            int idx = i * 256 + t;
            int row = idx >> 5, c4 = (idx & 31) * 4;
            float4 kv = *(const float4*)(Kt + row * 128 + c4);
            float4 vv = *(const float4*)(Vt + row * 128 + c4);
            float* dk = Ks + row * 132 + c4;
            dk[0] = tf32f(kv.x); dk[1] = tf32f(kv.y); dk[2] = tf32f(kv.z); dk[3] = tf32f(kv.w);
            float* dv = Vs + row * 136 + c4;
            dv[0] = tf32f(vv.x); dv[1] = tf32f(vv.y); dv[2] = tf32f(vv.z); dv[3] = tf32f(vv.w);
        }
        __syncthreads();

        float Sr[8][4], Si[8][4];
        #pragma unroll
        for (int i = 0; i < 8; i++) {
            Sr[i][0] = 0.f; Sr[i][1] = 0.f; Sr[i][2] = 0.f; Sr[i][3] = 0.f;
            Si[i][0] = 0.f; Si[i][1] = 0.f; Si[i][2] = 0.f; Si[i][3] = 0.f;
        }

        #pragma unroll 2
        for (int ks = 0; ks < 8; ks++) {
            const int col = 8 * ks + tg;
            const float* q0p = Qs + (qrow + g) * 132;
            const float* q8p = Qs + (qrow + g + 8) * 132;
            uint32_t ar0 = __float_as_uint(q0p[col]);
            uint32_t ar1 = __float_as_uint(q8p[col]);
            uint32_t ar2 = __float_as_uint(q0p[col + 4]);
            uint32_t ar3 = __float_as_uint(q8p[col + 4]);
            uint32_t ai0 = __float_as_uint(q0p[col + 64]);
            uint32_t ai1 = __float_as_uint(q8p[col + 64]);
            uint32_t ai2 = __float_as_uint(q0p[col + 68]);
            uint32_t ai3 = __float_as_uint(q8p[col + 68]);
            uint32_t nr0 = ar0 ^ 0x80000000u, nr1 = ar1 ^ 0x80000000u;
            uint32_t nr2 = ar2 ^ 0x80000000u, nr3 = ar3 ^ 0x80000000u;
            #pragma unroll
            for (int nt = 0; nt < 8; nt++) {
                const float* kp = Ks + (8 * nt + g) * 132 + col;
                uint32_t br0 = __float_as_uint(kp[0]);
                uint32_t br1 = __float_as_uint(kp[4]);
                uint32_t bi0 = __float_as_uint(kp[64]);
                uint32_t bi1 = __float_as_uint(kp[68]);
                mma8(Sr[nt], ar0, ar1, ar2, ar3, br0, br1);  // qr.kr
                mma8(Sr[nt], ai0, ai1, ai2, ai3, bi0, bi1);  // + qi.ki
                mma8(Si[nt], ai0, ai1, ai2, ai3, br0, br1);  // qi.kr
                mma8(Si[nt], nr0, nr1, nr2, nr3, bi0, bi1);  // - qr.ki
            }
        }

        // magnitude + exp on FMA/ALU pipes; accumulate l; store P
        #pragma unroll
        for (int nt = 0; nt < 8; nt++) {
            float h0 = fmaf(Si[nt][0], Si[nt][0], Sr[nt][0] * Sr[nt][0]);
            float h1 = fmaf(Si[nt][1], Si[nt][1], Sr[nt][1] * Sr[nt][1]);
            float h2 = fmaf(Si[nt][2], Si[nt][2], Sr[nt][2] * Sr[nt][2]);
            float h3 = fmaf(Si[nt][3], Si[nt][3], Sr[nt][3] * Sr[nt][3]);
            float p0 = exp2p(fmaf(sqrt_nr(h0), K1, K2));
            float p1 = exp2p(fmaf(sqrt_nr(h1), K1, K2));
            float p2 = exp2p(fmaf(sqrt_nr(h2), K1, K2));
            float p3 = exp2p(fmaf(sqrt_nr(h3), K1, K2));
            l0 += p0 + p1;
            l1 += p2 + p3;
            *(float2*)(Ps + (qrow + g) * 68 + 8 * nt + 2 * tg) = make_float2(tf32f(p0), tf32f(p1));
            *(float2*)(Ps + (qrow + g + 8) * 68 + 8 * nt + 2 * tg) = make_float2(tf32f(p2), tf32f(p3));
        }
        __syncwarp();   // each warp reads only its own 16 P rows

        // O += P @ [vr|vi]
        #pragma unroll 2
        for (int ks = 0; ks < 8; ks++) {
            const int pcol = 8 * ks + tg;
            uint32_t a0 = __float_as_uint(Ps[(qrow + g) * 68 + pcol]);
            uint32_t a1 = __float_as_uint(Ps[(qrow + g + 8) * 68 + pcol]);
            uint32_t a2 = __float_as_uint(Ps[(qrow + g) * 68 + pcol + 4]);
            uint32_t a3 = __float_as_uint(Ps[(qrow + g + 8) * 68 + pcol + 4]);
            const float* v0p = Vs + (8 * ks + tg) * 136 + g;
            const float* v1p = Vs + (8 * ks + tg + 4) * 136 + g;
            #pragma unroll
            for (int nt = 0; nt < 16; nt++) {
                uint32_t b0 = __float_as_uint(v0p[8 * nt]);
                uint32_t b1 = __float_as_uint(v1p[8 * nt]);
                mma8(O[nt], a0, a1, a2, a3, b0, b1);
            }
        }
    }

    // epilogue: divide by row sums, write merged-head layout into g_z
    l0 += __shfl_xor_sync(0xffffffffu, l0, 1);
    l0 += __shfl_xor_sync(0xffffffffu, l0, 2);
    l1 += __shfl_xor_sync(0xffffffffu, l1, 1);
    l1 += __shfl_xor_sync(0xffffffffu, l1, 2);
    const float inv0 = 1.f / l0, inv1 = 1.f / l1;

    const int b_ = bh >> 4, hh = bh & 15;
    const int q = q0 + qrow + g;
    float* dst0 = g_z + (size_t)(b_ * 2048 + q) * 2048;
    float* dst1 = g_z + (size_t)(b_ * 2048 + q + 8) * 2048;
    #pragma unroll
    for (int nt = 0; nt < 16; nt++) {
        int d0 = 8 * nt + 2 * tg;
        int col = (d0 >> 6) * 1024 + hh * 64 + (d0 & 63);
        *(float2*)(dst0 + col) = make_float2(O[nt][0] * inv0, O[nt][1] * inv0);
        *(float2*)(dst1 + col) = make_float2(O[nt][2] * inv1, O[nt][3] * inv1);
    }
}

// ---------------------------------------------------------------------------
// Final GEMM: out[m][o] = sum_k g_z[m][k]*Wc[o][k] + (1.1*or_b - 0.9*oi_b)[o]
// Wc on the fly: k<1024: or_w + 0.1*oi_w ; k>=1024: 0.1*or_w - oi_w.
// M=4096, N=1024, K=2048.
// ---------------------------------------------------------------------------
__global__ void __launch_bounds__(256) final_mma_kernel(
    const float* __restrict__ orw, const float* __restrict__ orb,
    const float* __restrict__ oiw, const float* __restrict__ oib,
    float* __restrict__ Outp)
{
    extern __shared__ float sm[];
    float* As = sm;
    float* Bs = sm + 2 * 128 * 36;

    const int t = threadIdx.x;
    const int w = t >> 5, lane = t & 31, g = lane >> 2, tg = lane & 3;
    const int wm = w >> 2, wn = w & 3;
    const int m0 = blockIdx.y * 128;
    const int o0 = blockIdx.x * 128;

    int lrow[4], lc4[4];
    #pragma unroll
    for (int i = 0; i < 4; i++) { int idx = i * 256 + t; lrow[i] = idx >> 3; lc4[i] = (idx & 7) * 4; }

    const float* Ag = g_z + (size_t)m0 * 2048;

    float acc[4][4][4];
    #pragma unroll
    for (int a = 0; a < 4; a++)
        #pragma unroll
        for (int b = 0; b < 4; b++)
            #pragma unroll
            for (int c = 0; c < 4; c++) acc[a][b][c] = 0.f;

    float4 pa[4], pb[4];
    #pragma unroll
    for (int i = 0; i < 4; i++) {
        pa[i] = *(const float4*)(Ag + lrow[i] * 2048 + lc4[i]);
        float4 a4 = *(const float4*)(orw + (size_t)(o0 + lrow[i]) * 1024 + lc4[i]);
        float4 b4 = *(const float4*)(oiw + (size_t)(o0 + lrow[i]) * 1024 + lc4[i]);
        pb[i] = make_float4(fmaf(0.1f, b4.x, a4.x), fmaf(0.1f, b4.y, a4.y),
                            fmaf(0.1f, b4.z, a4.z), fmaf(0.1f, b4.w, a4.w));
    }
    #pragma unroll
    for (int i = 0; i < 4; i++) {
        float* d = As + lrow[i] * 36 + lc4[i];
        d[0] = tf32f(pa[i].x); d[1] = tf32f(pa[i].y); d[2] = tf32f(pa[i].z); d[3] = tf32f(pa[i].w);
        float* e = Bs + lrow[i] * 36 + lc4[i];
        e[0] = tf32f(pb[i].x); e[1] = tf32f(pb[i].y); e[2] = tf32f(pb[i].z); e[3] = tf32f(pb[i].w);
    }
    __syncthreads();

    for (int ktile = 0; ktile < 64; ktile++) {
        const int cur = ktile & 1;
        if (ktile + 1 < 64) {
            int k0 = (ktile + 1) * 32;
            bool lo = k0 < 1024;
            int kk = lo ? k0 : (k0 - 1024);
            #pragma unroll
            for (int i = 0; i < 4; i++) {
                pa[i] = *(const float4*)(Ag + lrow[i] * 2048 + k0 + lc4[i]);
                float4 a4 = *(const float4*)(orw + (size_t)(o0 + lrow[i]) * 1024 + kk + lc4[i]);
                float4 b4 = *(const float4*)(oiw + (size_t)(o0 + lrow[i]) * 1024 + kk + lc4[i]);
                pb[i] = lo ? make_float4(fmaf(0.1f, b4.x, a4.x), fmaf(0.1f, b4.y, a4.y),
                                         fmaf(0.1f, b4.z, a4.z), fmaf(0.1f, b4.w, a4.w))
                           : make_float4(fmaf(0.1f, a4.x, -b4.x), fmaf(0.1f, a4.y, -b4.y),
                                         fmaf(0.1f, a4.z, -b4.z), fmaf(0.1f, a4.w, -b4.w));
            }
        }
        const float* Ab = As + cur * 128 * 36;
        const float* Bb = Bs + cur * 128 * 36;
        #pragma unroll
        for (int ks = 0; ks < 4; ks++) {
            const int col = 8 * ks + tg;
            uint32_t a[4][4];
            #pragma unroll
            for (int mt = 0; mt < 4; mt++) {
                const float* ap = Ab + (64 * wm + 16 * mt + g) * 36;
                a[mt][0] = __float_as_uint(ap[col]);
                a[mt][1] = __float_as_uint(ap[8 * 36 + col]);
                a[mt][2] = __float_as_uint(ap[col + 4]);
                a[mt][3] = __float_as_uint(ap[8 * 36 + col + 4]);
            }
            #pragma unroll
            for (int nt = 0; nt < 4; nt++) {
                const float* bp = Bb + (32 * wn + 8 * nt + g) * 36;
                uint32_t b0 = __float_as_uint(bp[col]);
                uint32_t b1 = __float_as_uint(bp[col + 4]);
                #pragma unroll
                for (int mt = 0; mt < 4; mt++)
                    mma8(acc[mt][nt], a[mt][0], a[mt][1], a[mt][2], a[mt][3], b0, b1);
            }
        }
        if (ktile + 1 < 64) {
            float* dA = As + (1 - cur) * 128 * 36;
            float* dB = Bs + (1 - cur) * 128 * 36;
            #pragma unroll
            for (int i = 0; i < 4; i++) {
                float* d = dA + lrow[i] * 36 + lc4[i];
                d[0] = tf32f(pa[i].x); d[1] = tf32f(pa[i].y); d[2] = tf32f(pa[i].z); d[3] = tf32f(pa[i].w);
                float* e = dB + lrow[i] * 36 + lc4[i];
                e[0] = tf32f(pb[i].x); e[1] = tf32f(pb[i].y); e[2] = tf32f(pb[i].z); e[3] = tf32f(pb[i].w);
            }
        }
        __syncthreads();
    }

    const int ob = o0 + 32 * wn;
    #pragma unroll
    for (int mt = 0; mt < 4; mt++) {
        int m = m0 + 64 * wm + 16 * mt + g;
        #pragma unroll
        for (int r = 0; r < 2; r++) {
            int mm = m + 8 * r;
            float* dst = Outp + (size_t)mm * 1024;
            #pragma unroll
            for (int nt = 0; nt < 4; nt++) {
                int o = ob + 8 * nt + 2 * tg;
                float2 ra = *(const float2*)(orb + o);
                float2 rb = *(const float2*)(oib + o);
                *(float2*)(dst + o) =
                    make_float2(acc[mt][nt][2 * r + 0] + 1.1f * ra.x - 0.9f * rb.x,
                                acc[mt][nt][2 * r + 1] + 1.1f * ra.y - 0.9f * rb.y);
            }
        }
    }
}

// ---------------------------------------------------------------------------
extern "C" void kernel_launch(void* const* d_in, const int* in_sizes, int n_in,
                              void* d_out, int out_size)
{
    const float* x    = (const float*)d_in[0];
    const float* qr_w = (const float*)d_in[1];
    const float* qr_b = (const float*)d_in[2];
    const float* qi_w = (const float*)d_in[3];
    const float* qi_b = (const float*)d_in[4];
    const float* kr_w = (const float*)d_in[5];
    const float* kr_b = (const float*)d_in[6];
    const float* ki_w = (const float*)d_in[7];
    const float* ki_b = (const float*)d_in[8];
    const float* vr_w = (const float*)d_in[9];
    const float* vr_b = (const float*)d_in[10];
    const float* vi_w = (const float*)d_in[11];
    const float* vi_b = (const float*)d_in[12];
    const float* or_w = (const float*)d_in[13];
    const float* or_b = (const float*)d_in[14];
    const float* oi_w = (const float*)d_in[15];
    const float* oi_b = (const float*)d_in[16];
    float* out = (float*)d_out;

    static bool attr_set = false;
    if (!attr_set) {
        cudaFuncSetAttribute(proj_mma_kernel, cudaFuncAttributeMaxDynamicSharedMemorySize, PROJ_SMEM);
        cudaFuncSetAttribute(attn_mma_kernel, cudaFuncAttributeMaxDynamicSharedMemorySize, ATT_SMEM);
        cudaFuncSetAttribute(final_mma_kernel, cudaFuncAttributeMaxDynamicSharedMemorySize, PROJ_SMEM);
        attr_set = true;
    }

    proj_mma_kernel<<<dim3(16, 32, 3), 256, PROJ_SMEM>>>(
        x, qr_w, qr_b, qi_w, qi_b, kr_w, kr_b, ki_w, ki_b,
        vr_w, vr_b, vi_w, vi_b);

    attn_mma_kernel<<<dim3(16, 32), 256, ATT_SMEM>>>();

    final_mma_kernel<<<dim3(8, 32), 256, PROJ_SMEM>>>(or_w, or_b, oi_w, oi_b, out);
}